// round 7
// baseline (speedup 1.0000x reference)
#include <cuda_runtime.h>

#define SEQ    4096
#define DM     1024
#define ZIPD   256
#define HEADS  8
#define DK     32      // ZIP / HEADS
#define DV     128     // DM / HEADS
#define NT     (SEQ/64)

// ---------------- scratch (static device globals; no allocation) ----------------
__device__ float g_qp[SEQ * ZIPD];   // Q' [s][zip]
__device__ float g_kp[SEQ * ZIPD];   // K' [s][zip]
__device__ float g_vr[SEQ * ZIPD];   // Vr [s][zip]
__device__ float g_vT[DM * SEQ];     // V transposed: g_vT[c][s]

// ---------------- packed f32x2 helpers ----------------
#define FMA2(d, a, b) \
    asm("fma.rn.f32x2 %0, %1, %2, %0;" : "+l"(d) : "l"(a), "l"(b))

__device__ __forceinline__ float hadd2(unsigned long long v) {
    float a, b;
    asm("mov.b64 {%0, %1}, %2;" : "=f"(a), "=f"(b) : "l"(v));
    return a + b;
}
__device__ __forceinline__ unsigned su32(const void* p) {
    unsigned a;
    asm("{.reg .u64 t; cvta.to.shared.u64 t, %1; cvt.u32.u64 %0, t;}"
        : "=r"(a) : "l"(p));
    return a;
}
__device__ __forceinline__ void cp16(unsigned d, const void* s) {
    asm volatile("cp.async.cg.shared.global [%0], [%1], 16;" :: "r"(d), "l"(s));
}
#define CP_COMMIT() asm volatile("cp.async.commit_group;")
#define CP_WAIT0()  asm volatile("cp.async.wait_group 0;")

// =====================================================================
// Packed-f32x2 GEMM: Y[M,N] = X[M,K] @ W[N,K]^T + bias
// BM=BN=64, BK=16, 256 threads, 4x4 per-thread tile, packed over K.
// Thread (tx,ty): rows m0+ty+16i, cols n0+tx+16j  (strided -> conflict-free
// b64 smem reads: bank stride 18 per lane hits all 32 banks).
// ROW_BIAS: bias indexed by m (used when computing V^T directly).
// =====================================================================
template <bool ROW_BIAS>
__device__ __forceinline__ void gemm2_body(const float* __restrict__ X,
                                           const float* __restrict__ W,
                                           const float* __restrict__ B,
                                           float* __restrict__ Y,
                                           int N, int K)
{
    __shared__ __align__(16) float Xs[64 * 18];   // [m][k], pad 18
    __shared__ __align__(16) float Ws[64 * 18];   // [n][k], pad 18

    const int tid  = threadIdx.x;
    const int tx   = tid & 15;
    const int ty   = tid >> 4;
    const int m0   = blockIdx.y * 64;
    const int n0   = blockIdx.x * 64;
    const int lrow = tid >> 2;        // 0..63
    const int lc4  = (tid & 3) * 4;   // 0,4,8,12

    unsigned long long acc[4][4];
#pragma unroll
    for (int i = 0; i < 4; ++i)
#pragma unroll
        for (int j = 0; j < 4; ++j) acc[i][j] = 0ULL;

    const float* Xg = &X[(m0 + lrow) * K + lc4];
    const float* Wg = &W[(n0 + lrow) * K + lc4];

    for (int kk0 = 0; kk0 < K; kk0 += 16) {
        float4 xa = *(const float4*)&Xg[kk0];
        float4 wa = *(const float4*)&Wg[kk0];
        __syncthreads();
        *(float2*)&Xs[lrow * 18 + lc4]     = make_float2(xa.x, xa.y);
        *(float2*)&Xs[lrow * 18 + lc4 + 2] = make_float2(xa.z, xa.w);
        *(float2*)&Ws[lrow * 18 + lc4]     = make_float2(wa.x, wa.y);
        *(float2*)&Ws[lrow * 18 + lc4 + 2] = make_float2(wa.z, wa.w);
        __syncthreads();

#pragma unroll
        for (int k2 = 0; k2 < 8; ++k2) {
            unsigned long long x2[4], w2[4];
#pragma unroll
            for (int i = 0; i < 4; ++i)
                x2[i] = *(const unsigned long long*)&Xs[(ty + 16 * i) * 18 + 2 * k2];
#pragma unroll
            for (int j = 0; j < 4; ++j)
                w2[j] = *(const unsigned long long*)&Ws[(tx + 16 * j) * 18 + 2 * k2];
#pragma unroll
            for (int i = 0; i < 4; ++i)
#pragma unroll
                for (int j = 0; j < 4; ++j)
                    FMA2(acc[i][j], x2[i], w2[j]);
        }
    }

#pragma unroll
    for (int i = 0; i < 4; ++i) {
        int m = m0 + ty + 16 * i;
#pragma unroll
        for (int j = 0; j < 4; ++j) {
            int n = n0 + tx + 16 * j;
            float bias = ROW_BIAS ? B[m] : B[n];
            Y[m * N + n] = hadd2(acc[i][j]) + bias;
        }
    }
}

// Three low-rank projections batched over blockIdx.z.
__global__ __launch_bounds__(256) void proj3_kernel(
    const float* __restrict__ q,  const float* __restrict__ k,  const float* __restrict__ v,
    const float* __restrict__ wq, const float* __restrict__ wk, const float* __restrict__ wvr,
    const float* __restrict__ bq, const float* __restrict__ bk, const float* __restrict__ bvr)
{
    const float* X; const float* W; const float* B; float* Y;
    if (blockIdx.z == 0)      { X = q; W = wq;  B = bq;  Y = g_qp; }
    else if (blockIdx.z == 1) { X = k; W = wk;  B = bk;  Y = g_kp; }
    else                      { X = v; W = wvr; B = bvr; Y = g_vr; }
    gemm2_body<false>(X, W, B, Y, ZIPD, DM);
}

// V up-projection, computed TRANSPOSED: g_vT[c][s] = sum_z wvl[c][z]*vr[s][z] + bvl[c]
// (X = w_v_l [1024,256], W = g_vr [4096,256], row-bias) -> coalesced everywhere.
__global__ __launch_bounds__(256) void projv_kernel(const float* __restrict__ wvl,
                                                    const float* __restrict__ bvl)
{
    gemm2_body<true>(wvl, g_vr, bvl, g_vT, SEQ, ZIPD);
}

// =====================================================================
// Flash attention, fp32 FFMA2, no 1/sqrt(dk) scaling, full softmax.
// Grid (SEQ/64, HEADS), 256 threads = 8 warps, warp owns 8 q-rows.
// QK packed over dk (Q,K row-major, NO transpose); PV packed over k
// (V staged column-major from g_vT). K/V double-buffered via cp.async.
// Lane cols: QK -> {lane, lane+32}; PV -> {lane+32j}.
// =====================================================================
#define QS_LD 36
#define KS_LD 36
#define VS_LD 68
#define FLASH_SMEM_FLOATS (64*QS_LD + 2*64*KS_LD + 2*128*VS_LD + 8*8*64)
#define FLASH_SMEM_BYTES  (FLASH_SMEM_FLOATS * 4)

__global__ __launch_bounds__(256) void flash_kernel(float* __restrict__ out)
{
    extern __shared__ float sm[];
    float* Qs  = sm;                         // [64][36]
    float* KsB = Qs  + 64 * QS_LD;           // 2 x [64][36]
    float* VsB = KsB + 2 * 64 * KS_LD;       // 2 x [128][68]   (V columns)
    float* Ps  = VsB + 2 * 128 * VS_LD;      // [8 warps][8 r][64]

    const int tid  = threadIdx.x;
    const int lane = tid & 31;
    const int warp = tid >> 5;
    const int h    = blockIdx.y;
    const int s0q  = blockIdx.x * 64;
    const int r0   = warp * 8;
    float* Psw = Ps + warp * 512;

    const int row = tid >> 3;            // 0..31
    const int d4  = (tid & 7) * 4;       // 0..28

    // ---- stage Q once (row-major, no transpose) ----
#pragma unroll
    for (int p = 0; p < 2; ++p) {
        int rr = p * 32 + row;
        *(float4*)&Qs[rr * QS_LD + d4] =
            *(const float4*)&g_qp[(s0q + rr) * ZIPD + h * DK + d4];
    }

    // ---- prologue: cp.async tile 0 into buffer 0 ----
    {
#pragma unroll
        for (int p = 0; p < 2; ++p) {
            int rr = p * 32 + row;
            cp16(su32(&KsB[rr * KS_LD + d4]),
                 &g_kp[rr * ZIPD + h * DK + d4]);
        }
#pragma unroll
        for (int i = 0; i < 8; ++i) {
            int f = tid + 256 * i, c = f >> 4, k4 = (f & 15) * 4;
            cp16(su32(&VsB[c * VS_LD + k4]),
                 &g_vT[(h * DV + c) * SEQ + k4]);
        }
        CP_COMMIT();
    }

    float O[8][4], m_r[8], l_r[8];
#pragma unroll
    for (int r = 0; r < 8; ++r) {
        m_r[r] = -1e30f; l_r[r] = 0.f;
        O[r][0] = O[r][1] = O[r][2] = O[r][3] = 0.f;
    }

    for (int t = 0; t < NT; ++t) {
        float* Ks = KsB + (t & 1) * (64 * KS_LD);
        float* Vs = VsB + (t & 1) * (128 * VS_LD);

        CP_WAIT0();
        __syncthreads();     // tile t ready; all warps done with buffer (t+1)&1

        if (t + 1 < NT) {    // prefetch tile t+1 (overlaps compute below)
            int s1 = (t + 1) * 64;
            float* Kn = KsB + ((t + 1) & 1) * (64 * KS_LD);
            float* Vn = VsB + ((t + 1) & 1) * (128 * VS_LD);
#pragma unroll
            for (int p = 0; p < 2; ++p) {
                int rr = p * 32 + row;
                cp16(su32(&Kn[rr * KS_LD + d4]),
                     &g_kp[(s1 + rr) * ZIPD + h * DK + d4]);
            }
#pragma unroll
            for (int i = 0; i < 8; ++i) {
                int f = tid + 256 * i, c = f >> 4, k4 = (f & 15) * 4;
                cp16(su32(&Vn[c * VS_LD + k4]),
                     &g_vT[(h * DV + c) * SEQ + s1 + k4]);
            }
            CP_COMMIT();
        }

        // ---- S = Q K^T, packed over dk ----
        unsigned long long a0[8], a1[8];
#pragma unroll
        for (int r = 0; r < 8; ++r) { a0[r] = 0ULL; a1[r] = 0ULL; }
        const float* K0 = &Ks[lane * KS_LD];
        const float* K1 = &Ks[(lane + 32) * KS_LD];
#pragma unroll
        for (int d2 = 0; d2 < 8; ++d2) {
            ulonglong2 k0 = *(const ulonglong2*)&K0[4 * d2];
            ulonglong2 k1 = *(const ulonglong2*)&K1[4 * d2];
#pragma unroll
            for (int r = 0; r < 8; ++r) {
                ulonglong2 qv = *(const ulonglong2*)&Qs[(r0 + r) * QS_LD + 4 * d2];
                FMA2(a0[r], qv.x, k0.x); FMA2(a0[r], qv.y, k0.y);
                FMA2(a1[r], qv.x, k1.x); FMA2(a1[r], qv.y, k1.y);
            }
        }

        // ---- online softmax (warp-local per row) ----
#pragma unroll
        for (int r = 0; r < 8; ++r) {
            float s0 = hadd2(a0[r]);
            float s1 = hadd2(a1[r]);
            float mx = fmaxf(s0, s1);
#pragma unroll
            for (int off = 16; off > 0; off >>= 1)
                mx = fmaxf(mx, __shfl_xor_sync(0xffffffffu, mx, off));
            float mnew  = fmaxf(m_r[r], mx);
            float scale = __expf(m_r[r] - mnew);
            float p0 = __expf(s0 - mnew);
            float p1 = __expf(s1 - mnew);
            float rs = p0 + p1;
#pragma unroll
            for (int off = 16; off > 0; off >>= 1)
                rs += __shfl_xor_sync(0xffffffffu, rs, off);
            l_r[r] = l_r[r] * scale + rs;
            m_r[r] = mnew;
            O[r][0] *= scale; O[r][1] *= scale;
            O[r][2] *= scale; O[r][3] *= scale;
            Psw[r * 64 + lane]      = p0;
            Psw[r * 64 + 32 + lane] = p1;
        }
        __syncwarp();

        // ---- O += P @ V, packed over k (V column-major in smem) ----
        unsigned long long oa[8][4];
#pragma unroll
        for (int r = 0; r < 8; ++r)
            oa[r][0] = oa[r][1] = oa[r][2] = oa[r][3] = 0ULL;
        const float* V0 = &Vs[(lane +  0) * VS_LD];
        const float* V1 = &Vs[(lane + 32) * VS_LD];
        const float* V2 = &Vs[(lane + 64) * VS_LD];
        const float* V3 = &Vs[(lane + 96) * VS_LD];
#pragma unroll
        for (int k2 = 0; k2 < 16; ++k2) {
            ulonglong2 v0 = *(const ulonglong2*)&V0[4 * k2];
            ulonglong2 v1 = *(const ulonglong2*)&V1[4 * k2];
            ulonglong2 v2 = *(const ulonglong2*)&V2[4 * k2];
            ulonglong2 v3 = *(const ulonglong2*)&V3[4 * k2];
#pragma unroll
            for (int r = 0; r < 8; ++r) {
                ulonglong2 p = *(const ulonglong2*)&Psw[r * 64 + 4 * k2];
                FMA2(oa[r][0], p.x, v0.x); FMA2(oa[r][0], p.y, v0.y);
                FMA2(oa[r][1], p.x, v1.x); FMA2(oa[r][1], p.y, v1.y);
                FMA2(oa[r][2], p.x, v2.x); FMA2(oa[r][2], p.y, v2.y);
                FMA2(oa[r][3], p.x, v3.x); FMA2(oa[r][3], p.y, v3.y);
            }
        }
#pragma unroll
        for (int r = 0; r < 8; ++r) {
            O[r][0] += hadd2(oa[r][0]); O[r][1] += hadd2(oa[r][1]);
            O[r][2] += hadd2(oa[r][2]); O[r][3] += hadd2(oa[r][3]);
        }
    }

    // ---- epilogue: normalize + store (lanes consecutive -> coalesced) ----
#pragma unroll
    for (int r = 0; r < 8; ++r) {
        float inv = 1.0f / l_r[r];
        int orow = s0q + r0 + r;
#pragma unroll
        for (int j = 0; j < 4; ++j)
            out[orow * DM + h * DV + lane + 32 * j] = O[r][j] * inv;
    }
}

// =====================================================================
// launch
// =====================================================================
extern "C" void kernel_launch(void* const* d_in, const int* in_sizes, int n_in,
                              void* d_out, int out_size)
{
    (void)in_sizes; (void)n_in; (void)out_size;
    const float* q   = (const float*)d_in[0];
    const float* k   = (const float*)d_in[1];
    const float* v   = (const float*)d_in[2];
    const float* wq  = (const float*)d_in[3];
    const float* bq  = (const float*)d_in[4];
    const float* wk  = (const float*)d_in[5];
    const float* bk  = (const float*)d_in[6];
    const float* wvr = (const float*)d_in[7];
    const float* bvr = (const float*)d_in[8];
    const float* wvl = (const float*)d_in[9];
    const float* bvl = (const float*)d_in[10];
    float* out = (float*)d_out;

    // 1) Q', K', Vr projections
    dim3 g1(ZIPD / 64, SEQ / 64, 3);
    proj3_kernel<<<g1, 256>>>(q, k, v, wq, wk, wvr, bq, bk, bvr);

    // 2) V up-projection, written transposed into g_vT
    dim3 g2(SEQ / 64, DM / 64);
    projv_kernel<<<g2, 256>>>(wvl, bvl);

    // 3) flash attention (113.6 KB dynamic smem -> opt-in)
    cudaFuncSetAttribute(flash_kernel,
                         cudaFuncAttributeMaxDynamicSharedMemorySize,
                         FLASH_SMEM_BYTES);
    dim3 g3(SEQ / 64, HEADS);
    flash_kernel<<<g3, 256, FLASH_SMEM_BYTES>>>(out);
}

// round 8
// speedup vs baseline: 2.4848x; 2.4848x over previous
#include <cuda_runtime.h>
#include <cuda_bf16.h>

#define SEQ    4096
#define DM     1024
#define ZIPD   256
#define HEADS  8
#define DK     32      // ZIP / HEADS
#define DV     128     // DM / HEADS
#define BQ     64      // q rows per CTA (4 warps x 16)
#define BK     64      // kv rows per tile
#define NT     (SEQ/BK)

// ---------------- scratch (static device globals; no allocation) ----------------
__device__ float g_vr[SEQ * ZIPD];                         // Vr fp32 (intermediate)
__device__ __align__(16) __nv_bfloat16 g_qph[SEQ * ZIPD];  // Q' hi  [s][zip]
__device__ __align__(16) __nv_bfloat16 g_qpl[SEQ * ZIPD];  // Q' lo
__device__ __align__(16) __nv_bfloat16 g_kph[SEQ * ZIPD];  // K' hi
__device__ __align__(16) __nv_bfloat16 g_kpl[SEQ * ZIPD];  // K' lo
__device__ __align__(16) __nv_bfloat16 g_vth[DM * SEQ];    // V^T hi [c][s]
__device__ __align__(16) __nv_bfloat16 g_vtl[DM * SEQ];    // V^T lo

// ---------------- small helpers ----------------
__device__ __forceinline__ unsigned su32(const void* p) {
    unsigned a;
    asm("{.reg .u64 t; cvta.to.shared.u64 t, %1; cvt.u32.u64 %0, t;}"
        : "=r"(a) : "l"(p));
    return a;
}
__device__ __forceinline__ void cp16(unsigned d, const void* s) {
    asm volatile("cp.async.cg.shared.global [%0], [%1], 16;" :: "r"(d), "l"(s));
}
#define CP_COMMIT() asm volatile("cp.async.commit_group;")
#define CP_WAIT0()  asm volatile("cp.async.wait_group 0;")

__device__ __forceinline__ void ldm4(unsigned* d, unsigned addr) {
    asm volatile("ldmatrix.sync.aligned.m8n8.x4.shared.b16 {%0,%1,%2,%3}, [%4];"
                 : "=r"(d[0]), "=r"(d[1]), "=r"(d[2]), "=r"(d[3]) : "r"(addr));
}
__device__ __forceinline__ void mma16816(float* c, const unsigned* a,
                                         unsigned b0, unsigned b1) {
    asm volatile(
        "mma.sync.aligned.m16n8k16.row.col.f32.bf16.bf16.f32 "
        "{%0,%1,%2,%3}, {%4,%5,%6,%7}, {%8,%9}, {%0,%1,%2,%3};"
        : "+f"(c[0]), "+f"(c[1]), "+f"(c[2]), "+f"(c[3])
        : "r"(a[0]), "r"(a[1]), "r"(a[2]), "r"(a[3]), "r"(b0), "r"(b1));
}
// pack two floats into bf16x2 hi + residual-lo bf16x2
__device__ __forceinline__ void split2(float a, float b, unsigned& hi, unsigned& lo) {
    __nv_bfloat162 h, l;
    h.x = __float2bfloat16(a);
    h.y = __float2bfloat16(b);
    l.x = __float2bfloat16(a - __bfloat162float(h.x));
    l.y = __float2bfloat16(b - __bfloat162float(h.y));
    hi = *(unsigned*)&h;
    lo = *(unsigned*)&l;
}

// =====================================================================
// Scalar fp32 GEMM (R6, measured 216us for proj3): Y = X[M,K] @ W[N,K]^T + bias
// MODE 0: col-bias, split-store bf16 hi/lo   (Q', K')
// MODE 1: col-bias, fp32 store               (Vr)
// MODE 2: row-bias, split-store bf16 hi/lo   (V^T)
// =====================================================================
template <int MODE>
__device__ __forceinline__ void gemm_body(const float* __restrict__ X,
                                          const float* __restrict__ W,
                                          const float* __restrict__ Bv,
                                          float* __restrict__ Yf,
                                          __nv_bfloat16* __restrict__ Yh,
                                          __nv_bfloat16* __restrict__ Yl,
                                          int N, int K)
{
    __shared__ float Xs[16][68];
    __shared__ float Ws[16][68];

    const int tid = threadIdx.x;
    const int tx  = tid & 15;
    const int ty  = tid >> 4;
    const int m0  = blockIdx.y * 64;
    const int n0  = blockIdx.x * 64;
    const int lrow = tid >> 2;
    const int lc4  = (tid & 3) * 4;

    float acc[4][4];
#pragma unroll
    for (int i = 0; i < 4; ++i)
#pragma unroll
        for (int j = 0; j < 4; ++j) acc[i][j] = 0.f;

    for (int kk0 = 0; kk0 < K; kk0 += 16) {
        float4 xa = *(const float4*)&X[(m0 + lrow) * K + kk0 + lc4];
        float4 wa = *(const float4*)&W[(n0 + lrow) * K + kk0 + lc4];
        __syncthreads();
        Xs[lc4 + 0][lrow] = xa.x; Xs[lc4 + 1][lrow] = xa.y;
        Xs[lc4 + 2][lrow] = xa.z; Xs[lc4 + 3][lrow] = xa.w;
        Ws[lc4 + 0][lrow] = wa.x; Ws[lc4 + 1][lrow] = wa.y;
        Ws[lc4 + 2][lrow] = wa.z; Ws[lc4 + 3][lrow] = wa.w;
        __syncthreads();
#pragma unroll
        for (int kk = 0; kk < 16; ++kk) {
            float4 xm4 = *(const float4*)&Xs[kk][ty * 4];
            float4 wn4 = *(const float4*)&Ws[kk][tx * 4];
            float xm[4] = {xm4.x, xm4.y, xm4.z, xm4.w};
            float wn[4] = {wn4.x, wn4.y, wn4.z, wn4.w};
#pragma unroll
            for (int i = 0; i < 4; ++i)
#pragma unroll
                for (int j = 0; j < 4; ++j)
                    acc[i][j] += xm[i] * wn[j];
        }
    }

#pragma unroll
    for (int i = 0; i < 4; ++i) {
        int m = m0 + ty * 4 + i;
        float cb[4];
        if (MODE == 2) {
            float rb = Bv[m];
            cb[0] = cb[1] = cb[2] = cb[3] = rb;
        } else {
            float4 bb = *(const float4*)&Bv[n0 + tx * 4];
            cb[0] = bb.x; cb[1] = bb.y; cb[2] = bb.z; cb[3] = bb.w;
        }
        if (MODE == 1) {
            float4 o = make_float4(acc[i][0] + cb[0], acc[i][1] + cb[1],
                                   acc[i][2] + cb[2], acc[i][3] + cb[3]);
            *(float4*)&Yf[m * N + n0 + tx * 4] = o;
        } else {
#pragma unroll
            for (int j = 0; j < 4; ++j) {
                float vv = acc[i][j] + cb[j];
                __nv_bfloat16 hi = __float2bfloat16(vv);
                __nv_bfloat16 lo = __float2bfloat16(vv - __bfloat162float(hi));
                Yh[m * N + n0 + tx * 4 + j] = hi;
                Yl[m * N + n0 + tx * 4 + j] = lo;
            }
        }
    }
}

__global__ __launch_bounds__(256) void proj3_kernel(
    const float* __restrict__ q,  const float* __restrict__ k,  const float* __restrict__ v,
    const float* __restrict__ wq, const float* __restrict__ wk, const float* __restrict__ wvr,
    const float* __restrict__ bq, const float* __restrict__ bk, const float* __restrict__ bvr)
{
    if (blockIdx.z == 0)
        gemm_body<0>(q, wq, bq, nullptr, g_qph, g_qpl, ZIPD, DM);
    else if (blockIdx.z == 1)
        gemm_body<0>(k, wk, bk, nullptr, g_kph, g_kpl, ZIPD, DM);
    else
        gemm_body<1>(v, wvr, bvr, g_vr, nullptr, nullptr, ZIPD, DM);
}

// V^T[c][s] = sum_z wvl[c][z]*vr[s][z] + bvl[c], split-stored bf16 hi/lo
__global__ __launch_bounds__(256) void projv_kernel(const float* __restrict__ wvl,
                                                    const float* __restrict__ bvl)
{
    gemm_body<2>(wvl, g_vr, bvl, nullptr, g_vth, g_vtl, SEQ, ZIPD);
}

// =====================================================================
// Tensor-core flash attention (mma.sync m16n8k16 bf16, 3-term split).
// Grid (SEQ/64, HEADS), 128 threads = 4 warps; warp owns 16 q-rows.
// smem per buffer: Ksh[64][20u32] 5120B, Ksl 5120B,
//                  Vsh[128][36u32] 18432B, Vsl 18432B  -> 47104B; x2 buffers.
// =====================================================================
#define KS_STRIDE_B 80     // 20 u32
#define VS_STRIDE_B 144    // 36 u32
#define OFF_KSL     5120
#define OFF_VSH     10240
#define OFF_VSL     28672
#define BUFB        47104
#define FLASH_SMEM_BYTES (2 * BUFB)

__device__ __forceinline__ void load_tile(unsigned smb, int buf, int tid, int h, int s1)
{
    unsigned kh = smb + buf;
    unsigned kl = kh + OFF_KSL;
    unsigned vh = kh + OFF_VSH;
    unsigned vl = kh + OFF_VSL;
#pragma unroll
    for (int i = 0; i < 2; ++i) {
        int c = tid + 128 * i;
        int row = c >> 2, part = c & 3;
        size_t off = (size_t)(s1 + row) * ZIPD + h * DK + part * 8;
        cp16(kh + row * KS_STRIDE_B + part * 16, g_kph + off);
        cp16(kl + row * KS_STRIDE_B + part * 16, g_kpl + off);
    }
#pragma unroll
    for (int i = 0; i < 8; ++i) {
        int c = tid + 128 * i;
        int row = c >> 3, part = c & 7;
        size_t off = (size_t)(h * DV + row) * SEQ + s1 + part * 8;
        cp16(vh + row * VS_STRIDE_B + part * 16, g_vth + off);
        cp16(vl + row * VS_STRIDE_B + part * 16, g_vtl + off);
    }
    CP_COMMIT();
}

__global__ __launch_bounds__(128) void flash_kernel(float* __restrict__ out)
{
    extern __shared__ __align__(16) char smem[];
    const unsigned smb = su32(smem);

    const int tid  = threadIdx.x;
    const int lane = tid & 31;
    const int warp = tid >> 5;
    const int h    = blockIdx.y;
    const int s0q  = blockIdx.x * BQ;

    // mma accumulator lane coords
    const int qr = lane >> 2;        // row within 16-row group (rows qr, qr+8)
    const int qc = (lane & 3) * 2;   // col pair base

    // ldmatrix lane->address mapping (x4: matrix m = lane/8, row r = lane%8)
    const int lm_m = lane >> 3;
    const int lm_r = lane & 7;
    const int lm_n = 8 * (lm_m >> 1) + lm_r;     // n-row within 16-row pair
    const int lm_k = (lm_m & 1) * 16;            // k byte offset (8 bf16)

    // ---- load Q fragments once (direct gmem u32 reads) ----
    unsigned Qh[2][4], Ql[2][4];
    {
        int row0 = s0q + 16 * warp + qr;
#pragma unroll
        for (int kk = 0; kk < 2; ++kk) {
            int cb = h * DK + 16 * kk + qc;
            Qh[kk][0] = *(const unsigned*)&g_qph[row0 * ZIPD + cb];
            Qh[kk][1] = *(const unsigned*)&g_qph[(row0 + 8) * ZIPD + cb];
            Qh[kk][2] = *(const unsigned*)&g_qph[row0 * ZIPD + cb + 8];
            Qh[kk][3] = *(const unsigned*)&g_qph[(row0 + 8) * ZIPD + cb + 8];
            Ql[kk][0] = *(const unsigned*)&g_qpl[row0 * ZIPD + cb];
            Ql[kk][1] = *(const unsigned*)&g_qpl[(row0 + 8) * ZIPD + cb];
            Ql[kk][2] = *(const unsigned*)&g_qpl[row0 * ZIPD + cb + 8];
            Ql[kk][3] = *(const unsigned*)&g_qpl[(row0 + 8) * ZIPD + cb + 8];
        }
    }

    // prologue: tile 0 -> buffer 0
    load_tile(smb, 0, tid, h, 0);

    float O[16][4];
#pragma unroll
    for (int b = 0; b < 16; ++b)
        O[b][0] = O[b][1] = O[b][2] = O[b][3] = 0.f;
    float m0s = -1e30f, m1s = -1e30f, l0s = 0.f, l1s = 0.f;

    for (int t = 0; t < NT; ++t) {
        const int buf = (t & 1) * BUFB;

        CP_WAIT0();
        __syncthreads();
        if (t + 1 < NT)
            load_tile(smb, ((t + 1) & 1) * BUFB, tid, h, (t + 1) * BK);

        const unsigned ksh_a = smb + buf + lm_n * KS_STRIDE_B + lm_k;
        const unsigned ksl_a = ksh_a + OFF_KSL;
        const unsigned vsh_a = smb + buf + OFF_VSH + lm_n * VS_STRIDE_B + lm_k;
        const unsigned vsl_a = vsh_a + (OFF_VSL - OFF_VSH);

        // ---- S = Q K'^T  (3-term split) ----
        float S[8][4];
#pragma unroll
        for (int b = 0; b < 8; ++b)
            S[b][0] = S[b][1] = S[b][2] = S[b][3] = 0.f;
#pragma unroll
        for (int kk = 0; kk < 2; ++kk) {
#pragma unroll
            for (int bp = 0; bp < 4; ++bp) {
                unsigned kh[4], kl[4];
                ldm4(kh, ksh_a + bp * (16 * KS_STRIDE_B) + kk * 32);
                ldm4(kl, ksl_a + bp * (16 * KS_STRIDE_B) + kk * 32);
                mma16816(S[2 * bp],     Qh[kk], kh[0], kh[1]);
                mma16816(S[2 * bp],     Qh[kk], kl[0], kl[1]);
                mma16816(S[2 * bp],     Ql[kk], kh[0], kh[1]);
                mma16816(S[2 * bp + 1], Qh[kk], kh[2], kh[3]);
                mma16816(S[2 * bp + 1], Qh[kk], kl[2], kl[3]);
                mma16816(S[2 * bp + 1], Ql[kk], kh[2], kh[3]);
            }
        }

        // ---- online softmax (rows qr / qr+8; 64 cols spread over lane quad) ----
        float mx0 = -1e30f, mx1 = -1e30f;
#pragma unroll
        for (int b = 0; b < 8; ++b) {
            mx0 = fmaxf(mx0, fmaxf(S[b][0], S[b][1]));
            mx1 = fmaxf(mx1, fmaxf(S[b][2], S[b][3]));
        }
        mx0 = fmaxf(mx0, __shfl_xor_sync(0xffffffffu, mx0, 1));
        mx0 = fmaxf(mx0, __shfl_xor_sync(0xffffffffu, mx0, 2));
        mx1 = fmaxf(mx1, __shfl_xor_sync(0xffffffffu, mx1, 1));
        mx1 = fmaxf(mx1, __shfl_xor_sync(0xffffffffu, mx1, 2));

        float mn0 = fmaxf(m0s, mx0);
        float mn1 = fmaxf(m1s, mx1);
        float sc0 = __expf(m0s - mn0);
        float sc1 = __expf(m1s - mn1);

        float rs0 = 0.f, rs1 = 0.f;
#pragma unroll
        for (int b = 0; b < 8; ++b) {
            S[b][0] = __expf(S[b][0] - mn0);
            S[b][1] = __expf(S[b][1] - mn0);
            S[b][2] = __expf(S[b][2] - mn1);
            S[b][3] = __expf(S[b][3] - mn1);
            rs0 += S[b][0] + S[b][1];
            rs1 += S[b][2] + S[b][3];
        }
        rs0 += __shfl_xor_sync(0xffffffffu, rs0, 1);
        rs0 += __shfl_xor_sync(0xffffffffu, rs0, 2);
        rs1 += __shfl_xor_sync(0xffffffffu, rs1, 1);
        rs1 += __shfl_xor_sync(0xffffffffu, rs1, 2);
        l0s = l0s * sc0 + rs0;  m0s = mn0;
        l1s = l1s * sc1 + rs1;  m1s = mn1;

#pragma unroll
        for (int b = 0; b < 16; ++b) {
            O[b][0] *= sc0; O[b][1] *= sc0;
            O[b][2] *= sc1; O[b][3] *= sc1;
        }

        // ---- O += P V  (P repacked from S fragments in registers) ----
#pragma unroll
        for (int kk = 0; kk < 4; ++kk) {
            unsigned pah[4], pal[4];
            split2(S[2 * kk][0],     S[2 * kk][1],     pah[0], pal[0]);
            split2(S[2 * kk][2],     S[2 * kk][3],     pah[1], pal[1]);
            split2(S[2 * kk + 1][0], S[2 * kk + 1][1], pah[2], pal[2]);
            split2(S[2 * kk + 1][2], S[2 * kk + 1][3], pah[3], pal[3]);
#pragma unroll
            for (int bp = 0; bp < 8; ++bp) {
                unsigned vh[4], vl[4];
                ldm4(vh, vsh_a + bp * (16 * VS_STRIDE_B) + kk * 32);
                ldm4(vl, vsl_a + bp * (16 * VS_STRIDE_B) + kk * 32);
                mma16816(O[2 * bp],     pah, vh[0], vh[1]);
                mma16816(O[2 * bp],     pah, vl[0], vl[1]);
                mma16816(O[2 * bp],     pal, vh[0], vh[1]);
                mma16816(O[2 * bp + 1], pah, vh[2], vh[3]);
                mma16816(O[2 * bp + 1], pah, vl[2], vl[3]);
                mma16816(O[2 * bp + 1], pal, vh[2], vh[3]);
            }
        }
    }

    // ---- epilogue: normalize, write fp32 out ----
    {
        float inv0 = 1.0f / l0s;
        float inv1 = 1.0f / l1s;
        int row0 = s0q + 16 * warp + qr;
        int row1 = row0 + 8;
#pragma unroll
        for (int b = 0; b < 16; ++b) {
            int col = h * DV + 8 * b + qc;
            *(float2*)&out[row0 * DM + col] = make_float2(O[b][0] * inv0, O[b][1] * inv0);
            *(float2*)&out[row1 * DM + col] = make_float2(O[b][2] * inv1, O[b][3] * inv1);
        }
    }
}

// =====================================================================
// launch
// =====================================================================
extern "C" void kernel_launch(void* const* d_in, const int* in_sizes, int n_in,
                              void* d_out, int out_size)
{
    (void)in_sizes; (void)n_in; (void)out_size;
    const float* q   = (const float*)d_in[0];
    const float* k   = (const float*)d_in[1];
    const float* v   = (const float*)d_in[2];
    const float* wq  = (const float*)d_in[3];
    const float* bq  = (const float*)d_in[4];
    const float* wk  = (const float*)d_in[5];
    const float* bk  = (const float*)d_in[6];
    const float* wvr = (const float*)d_in[7];
    const float* bvr = (const float*)d_in[8];
    const float* wvl = (const float*)d_in[9];
    const float* bvl = (const float*)d_in[10];
    float* out = (float*)d_out;

    // 1) Q', K' (split bf16) + Vr (fp32)
    dim3 g1(ZIPD / 64, SEQ / 64, 3);
    proj3_kernel<<<g1, 256>>>(q, k, v, wq, wk, wvr, bq, bk, bvr);

    // 2) V^T split bf16
    dim3 g2(SEQ / 64, DM / 64);
    projv_kernel<<<g2, 256>>>(wvl, bvl);

    // 3) tensor-core flash attention (92KB dynamic smem)
    cudaFuncSetAttribute(flash_kernel,
                         cudaFuncAttributeMaxDynamicSharedMemorySize,
                         FLASH_SMEM_BYTES);
    dim3 g3(SEQ / BQ, HEADS);
    flash_kernel<<<g3, 128, FLASH_SMEM_BYTES>>>(out);
}

// round 11
// speedup vs baseline: 3.1732x; 1.2770x over previous
#include <cuda_runtime.h>
#include <cuda_bf16.h>

#define SEQ    4096
#define DM     1024
#define ZIPD   256
#define HEADS  8
#define DK     32      // ZIP / HEADS
#define DV     128     // DM / HEADS
#define BQ     64      // q rows per CTA (4 warps x 16)
#define BK     64      // kv rows per tile
#define NT     (SEQ/BK)

// ---------------- scratch (static device globals; no allocation) ----------------
// converted inputs (hi/lo bf16 split)
__device__ __align__(16) __nv_bfloat16 cq_h[SEQ * DM],   cq_l[SEQ * DM];
__device__ __align__(16) __nv_bfloat16 ck_h[SEQ * DM],   ck_l[SEQ * DM];
__device__ __align__(16) __nv_bfloat16 cv_h[SEQ * DM],   cv_l[SEQ * DM];
__device__ __align__(16) __nv_bfloat16 cwq_h[ZIPD * DM], cwq_l[ZIPD * DM];
__device__ __align__(16) __nv_bfloat16 cwk_h[ZIPD * DM], cwk_l[ZIPD * DM];
__device__ __align__(16) __nv_bfloat16 cwr_h[ZIPD * DM], cwr_l[ZIPD * DM];
__device__ __align__(16) __nv_bfloat16 cwl_h[DM * ZIPD], cwl_l[DM * ZIPD];
// projection outputs (hi/lo bf16 split)
__device__ __align__(16) __nv_bfloat16 g_qph[SEQ * ZIPD], g_qpl[SEQ * ZIPD];
__device__ __align__(16) __nv_bfloat16 g_kph[SEQ * ZIPD], g_kpl[SEQ * ZIPD];
__device__ __align__(16) __nv_bfloat16 g_vrh[SEQ * ZIPD], g_vrl[SEQ * ZIPD];
__device__ __align__(16) __nv_bfloat16 g_vth[DM * SEQ],   g_vtl[DM * SEQ];  // V^T [c][s]

// ---------------- small helpers ----------------
__device__ __forceinline__ unsigned su32(const void* p) {
    unsigned a;
    asm("{.reg .u64 t; cvta.to.shared.u64 t, %1; cvt.u32.u64 %0, t;}"
        : "=r"(a) : "l"(p));
    return a;
}
__device__ __forceinline__ void cp16(unsigned d, const void* s) {
    asm volatile("cp.async.cg.shared.global [%0], [%1], 16;" :: "r"(d), "l"(s));
}
#define CP_COMMIT() asm volatile("cp.async.commit_group;")
#define CP_WAIT0()  asm volatile("cp.async.wait_group 0;")

__device__ __forceinline__ void ldm4(unsigned* d, unsigned addr) {
    asm volatile("ldmatrix.sync.aligned.m8n8.x4.shared.b16 {%0,%1,%2,%3}, [%4];"
                 : "=r"(d[0]), "=r"(d[1]), "=r"(d[2]), "=r"(d[3]) : "r"(addr));
}
__device__ __forceinline__ void mma16816(float* c, const unsigned* a,
                                         unsigned b0, unsigned b1) {
    asm volatile(
        "mma.sync.aligned.m16n8k16.row.col.f32.bf16.bf16.f32 "
        "{%0,%1,%2,%3}, {%4,%5,%6,%7}, {%8,%9}, {%0,%1,%2,%3};"
        : "+f"(c[0]), "+f"(c[1]), "+f"(c[2]), "+f"(c[3])
        : "r"(a[0]), "r"(a[1]), "r"(a[2]), "r"(a[3]), "r"(b0), "r"(b1));
}
__device__ __forceinline__ void split2(float a, float b, unsigned& hi, unsigned& lo) {
    __nv_bfloat162 h, l;
    h.x = __float2bfloat16(a);
    h.y = __float2bfloat16(b);
    l.x = __float2bfloat16(a - __bfloat162float(h.x));
    l.y = __float2bfloat16(b - __bfloat162float(h.y));
    hi = *(unsigned*)&h;
    lo = *(unsigned*)&l;
}

// =====================================================================
// Convert fp32 -> bf16 hi/lo split (memory-bound pre-pass)
// =====================================================================
__global__ __launch_bounds__(256) void convert_qkv(const float* __restrict__ q,
                                                   const float* __restrict__ k,
                                                   const float* __restrict__ v)
{
    const float* s; __nv_bfloat16 *dh, *dl;
    if (blockIdx.y == 0)      { s = q; dh = cq_h; dl = cq_l; }
    else if (blockIdx.y == 1) { s = k; dh = ck_h; dl = ck_l; }
    else                      { s = v; dh = cv_h; dl = cv_l; }
    int i = (blockIdx.x * 256 + threadIdx.x) * 4;
    float4 x = *(const float4*)&s[i];
    unsigned h0, l0, h1, l1;
    split2(x.x, x.y, h0, l0);
    split2(x.z, x.w, h1, l1);
    *(uint2*)&dh[i] = make_uint2(h0, h1);
    *(uint2*)&dl[i] = make_uint2(l0, l1);
}

__global__ __launch_bounds__(256) void convert_w(const float* __restrict__ wq,
                                                 const float* __restrict__ wk,
                                                 const float* __restrict__ wvr,
                                                 const float* __restrict__ wvl)
{
    const float* s; __nv_bfloat16 *dh, *dl;
    if (blockIdx.y == 0)      { s = wq;  dh = cwq_h; dl = cwq_l; }
    else if (blockIdx.y == 1) { s = wk;  dh = cwk_h; dl = cwk_l; }
    else if (blockIdx.y == 2) { s = wvr; dh = cwr_h; dl = cwr_l; }
    else                      { s = wvl; dh = cwl_h; dl = cwl_l; }
    int i = (blockIdx.x * 256 + threadIdx.x) * 4;
    float4 x = *(const float4*)&s[i];
    unsigned h0, l0, h1, l1;
    split2(x.x, x.y, h0, l0);
    split2(x.z, x.w, h1, l1);
    *(uint2*)&dh[i] = make_uint2(h0, h1);
    *(uint2*)&dl[i] = make_uint2(l0, l1);
}

// =====================================================================
// mma projection GEMM: Y[M,N] = A[M,K] @ B[N,K]^T + bias, 3-term bf16 split,
// split-stored bf16 hi/lo. BM=128, BN=64, 256 threads (8 warps, warp=16x64).
// K staged 32 deep, double-buffered cp.async. smem stride 40 bf16 (80B):
// ldmatrix rows start at word 20r mod 32 -> all 8 quad-groups distinct.
// MODE 0: col-bias (bias[n]); MODE 1: row-bias (bias[m]).
// =====================================================================
#define PS_STRIDE_B 80
#define P_AH 0
#define P_AL 10240
#define P_BH 20480
#define P_BL 25600
#define P_BUF 30720
#define PROJ_SMEM_BYTES (2 * P_BUF)

template <int MODE>
__device__ __forceinline__ void proj_mma_body(
    const __nv_bfloat16* __restrict__ Ah, const __nv_bfloat16* __restrict__ Al,
    const __nv_bfloat16* __restrict__ Bh, const __nv_bfloat16* __restrict__ Bl,
    const float* __restrict__ bias,
    __nv_bfloat16* __restrict__ Yh, __nv_bfloat16* __restrict__ Yl,
    int K, int Nld)
{
    extern __shared__ __align__(16) char smem[];
    const unsigned smb = su32(smem);

    const int tid  = threadIdx.x;
    const int lane = tid & 31;
    const int warp = tid >> 5;
    const int m0   = blockIdx.y * 128;
    const int n0   = blockIdx.x * 64;

    const int qr = lane >> 2;
    const int qc = (lane & 3) * 2;
    // A-fragment ldmatrix map (row-major A, m16k16)
    const int a_row = ((lane >> 3) & 1) * 8 + (lane & 7);
    const int a_kb  = (lane >> 4) * 16;
    // B-fragment ldmatrix map (col-major B = [N,K] row-major, n16k16) — as in flash
    const int lm_m = lane >> 3;
    const int lm_r = lane & 7;
    const int lm_n = 8 * (lm_m >> 1) + lm_r;
    const int lm_k = (lm_m & 1) * 16;

    const int ld_row = tid >> 2;        // 0..63
    const int ld_prt = (tid & 3) * 8;   // bf16 col offset 0,8,16,24
    const int ld_prtB = (tid & 3) * 16; // byte offset

    float acc[8][4];
#pragma unroll
    for (int b = 0; b < 8; ++b)
        acc[b][0] = acc[b][1] = acc[b][2] = acc[b][3] = 0.f;

    const int nst = K / 32;

    // stage loader
    auto load_stage = [&](int buf, int kk) {
        unsigned base = smb + buf * P_BUF;
#pragma unroll
        for (int i = 0; i < 2; ++i) {
            int row = ld_row + 64 * i;   // 0..127
            cp16(base + P_AH + row * PS_STRIDE_B + ld_prtB,
                 Ah + (size_t)(m0 + row) * K + kk + ld_prt);
            cp16(base + P_AL + row * PS_STRIDE_B + ld_prtB,
                 Al + (size_t)(m0 + row) * K + kk + ld_prt);
        }
        cp16(base + P_BH + ld_row * PS_STRIDE_B + ld_prtB,
             Bh + (size_t)(n0 + ld_row) * K + kk + ld_prt);
        cp16(base + P_BL + ld_row * PS_STRIDE_B + ld_prtB,
             Bl + (size_t)(n0 + ld_row) * K + kk + ld_prt);
        CP_COMMIT();
    };

    load_stage(0, 0);

    for (int s = 0; s < nst; ++s) {
        const int buf = s & 1;
        CP_WAIT0();
        __syncthreads();
        if (s + 1 < nst) load_stage((s + 1) & 1, (s + 1) * 32);

        const unsigned ab = smb + buf * P_BUF +
                            (16 * warp + a_row) * PS_STRIDE_B + a_kb;
        const unsigned bb = smb + buf * P_BUF + P_BH +
                            lm_n * PS_STRIDE_B + lm_k;
#pragma unroll
        for (int ks = 0; ks < 2; ++ks) {
            unsigned aH[4], aL[4];
            ldm4(aH, ab + ks * 32);
            ldm4(aL, ab + P_AL + ks * 32);
#pragma unroll
            for (int nb = 0; nb < 4; ++nb) {
                unsigned bh[4], bl[4];
                ldm4(bh, bb + nb * (16 * PS_STRIDE_B) + ks * 32);
                ldm4(bl, bb + (P_BL - P_BH) + nb * (16 * PS_STRIDE_B) + ks * 32);
                mma16816(acc[2 * nb],     aH, bh[0], bh[1]);
                mma16816(acc[2 * nb],     aH, bl[0], bl[1]);
                mma16816(acc[2 * nb],     aL, bh[0], bh[1]);
                mma16816(acc[2 * nb + 1], aH, bh[2], bh[3]);
                mma16816(acc[2 * nb + 1], aH, bl[2], bl[3]);
                mma16816(acc[2 * nb + 1], aL, bh[2], bh[3]);
            }
        }
        __syncthreads();
    }

    // ---- epilogue: bias + split-store bf16 hi/lo ----
    const int r0 = m0 + 16 * warp + qr;
    const int r1 = r0 + 8;
    float br0 = 0.f, br1 = 0.f;
    if (MODE == 1) { br0 = bias[r0]; br1 = bias[r1]; }
#pragma unroll
    for (int b = 0; b < 8; ++b) {
        int col = n0 + 8 * b + qc;
        float b0, b1;
        if (MODE == 0) { b0 = bias[col]; b1 = bias[col + 1]; }
        float c0 = acc[b][0] + (MODE == 0 ? b0 : br0);
        float c1 = acc[b][1] + (MODE == 0 ? b1 : br0);
        float c2 = acc[b][2] + (MODE == 0 ? b0 : br1);
        float c3 = acc[b][3] + (MODE == 0 ? b1 : br1);
        unsigned h, l;
        split2(c0, c1, h, l);
        *(unsigned*)&Yh[(size_t)r0 * Nld + col] = h;
        *(unsigned*)&Yl[(size_t)r0 * Nld + col] = l;
        split2(c2, c3, h, l);
        *(unsigned*)&Yh[(size_t)r1 * Nld + col] = h;
        *(unsigned*)&Yl[(size_t)r1 * Nld + col] = l;
    }
}

__global__ __launch_bounds__(256) void proj3_mma(const float* __restrict__ bq,
                                                 const float* __restrict__ bk,
                                                 const float* __restrict__ bvr)
{
    if (blockIdx.z == 0)
        proj_mma_body<0>(cq_h, cq_l, cwq_h, cwq_l, bq, g_qph, g_qpl, DM, ZIPD);
    else if (blockIdx.z == 1)
        proj_mma_body<0>(ck_h, ck_l, cwk_h, cwk_l, bk, g_kph, g_kpl, DM, ZIPD);
    else
        proj_mma_body<0>(cv_h, cv_l, cwr_h, cwr_l, bvr, g_vrh, g_vrl, DM, ZIPD);
}

// V^T[c][s] = sum_z wvl[c][z]*Vr[s][z] + bvl[c]  (A = wvl, B = Vr, row-bias)
__global__ __launch_bounds__(256) void projv_mma(const float* __restrict__ bvl)
{
    proj_mma_body<1>(cwl_h, cwl_l, g_vrh, g_vrl, bvl, g_vth, g_vtl, ZIPD, SEQ);
}

// =====================================================================
// Tensor-core flash attention (unchanged from R8: validated at 1.8e-5).
// =====================================================================
#define KS_STRIDE_B 80
#define VS_STRIDE_B 144
#define OFF_KSL     5120
#define OFF_VSH     10240
#define OFF_VSL     28672
#define BUFB        47104
#define FLASH_SMEM_BYTES (2 * BUFB)

__device__ __forceinline__ void load_tile(unsigned smb, int buf, int tid, int h, int s1)
{
    unsigned kh = smb + buf;
    unsigned kl = kh + OFF_KSL;
    unsigned vh = kh + OFF_VSH;
    unsigned vl = kh + OFF_VSL;
#pragma unroll
    for (int i = 0; i < 2; ++i) {
        int c = tid + 128 * i;
        int row = c >> 2, part = c & 3;
        size_t off = (size_t)(s1 + row) * ZIPD + h * DK + part * 8;
        cp16(kh + row * KS_STRIDE_B + part * 16, g_kph + off);
        cp16(kl + row * KS_STRIDE_B + part * 16, g_kpl + off);
    }
#pragma unroll
    for (int i = 0; i < 8; ++i) {
        int c = tid + 128 * i;
        int row = c >> 3, part = c & 7;
        size_t off = (size_t)(h * DV + row) * SEQ + s1 + part * 8;
        cp16(vh + row * VS_STRIDE_B + part * 16, g_vth + off);
        cp16(vl + row * VS_STRIDE_B + part * 16, g_vtl + off);
    }
    CP_COMMIT();
}

__global__ __launch_bounds__(128) void flash_kernel(float* __restrict__ out)
{
    extern __shared__ __align__(16) char smem[];
    const unsigned smb = su32(smem);

    const int tid  = threadIdx.x;
    const int lane = tid & 31;
    const int warp = tid >> 5;
    const int h    = blockIdx.y;
    const int s0q  = blockIdx.x * BQ;

    const int qr = lane >> 2;
    const int qc = (lane & 3) * 2;
    const int lm_m = lane >> 3;
    const int lm_r = lane & 7;
    const int lm_n = 8 * (lm_m >> 1) + lm_r;
    const int lm_k = (lm_m & 1) * 16;

    unsigned Qh[2][4], Ql[2][4];
    {
        int row0 = s0q + 16 * warp + qr;
#pragma unroll
        for (int kk = 0; kk < 2; ++kk) {
            int cb = h * DK + 16 * kk + qc;
            Qh[kk][0] = *(const unsigned*)&g_qph[row0 * ZIPD + cb];
            Qh[kk][1] = *(const unsigned*)&g_qph[(row0 + 8) * ZIPD + cb];
            Qh[kk][2] = *(const unsigned*)&g_qph[row0 * ZIPD + cb + 8];
            Qh[kk][3] = *(const unsigned*)&g_qph[(row0 + 8) * ZIPD + cb + 8];
            Ql[kk][0] = *(const unsigned*)&g_qpl[row0 * ZIPD + cb];
            Ql[kk][1] = *(const unsigned*)&g_qpl[(row0 + 8) * ZIPD + cb];
            Ql[kk][2] = *(const unsigned*)&g_qpl[row0 * ZIPD + cb + 8];
            Ql[kk][3] = *(const unsigned*)&g_qpl[(row0 + 8) * ZIPD + cb + 8];
        }
    }

    load_tile(smb, 0, tid, h, 0);

    float O[16][4];
#pragma unroll
    for (int b = 0; b < 16; ++b)
        O[b][0] = O[b][1] = O[b][2] = O[b][3] = 0.f;
    float m0s = -1e30f, m1s = -1e30f, l0s = 0.f, l1s = 0.f;

    for (int t = 0; t < NT; ++t) {
        const int buf = (t & 1) * BUFB;

        CP_WAIT0();
        __syncthreads();
        if (t + 1 < NT)
            load_tile(smb, ((t + 1) & 1) * BUFB, tid, h, (t + 1) * BK);

        const unsigned ksh_a = smb + buf + lm_n * KS_STRIDE_B + lm_k;
        const unsigned ksl_a = ksh_a + OFF_KSL;
        const unsigned vsh_a = smb + buf + OFF_VSH + lm_n * VS_STRIDE_B + lm_k;
        const unsigned vsl_a = vsh_a + (OFF_VSL - OFF_VSH);

        float S[8][4];
#pragma unroll
        for (int b = 0; b < 8; ++b)
            S[b][0] = S[b][1] = S[b][2] = S[b][3] = 0.f;
#pragma unroll
        for (int kk = 0; kk < 2; ++kk) {
#pragma unroll
            for (int bp = 0; bp < 4; ++bp) {
                unsigned kh[4], kl[4];
                ldm4(kh, ksh_a + bp * (16 * KS_STRIDE_B) + kk * 32);
                ldm4(kl, ksl_a + bp * (16 * KS_STRIDE_B) + kk * 32);
                mma16816(S[2 * bp],     Qh[kk], kh[0], kh[1]);
                mma16816(S[2 * bp],     Qh[kk], kl[0], kl[1]);
                mma16816(S[2 * bp],     Ql[kk], kh[0], kh[1]);
                mma16816(S[2 * bp + 1], Qh[kk], kh[2], kh[3]);
                mma16816(S[2 * bp + 1], Qh[kk], kl[2], kl[3]);
                mma16816(S[2 * bp + 1], Ql[kk], kh[2], kh[3]);
            }
        }

        float mx0 = -1e30f, mx1 = -1e30f;
#pragma unroll
        for (int b = 0; b < 8; ++b) {
            mx0 = fmaxf(mx0, fmaxf(S[b][0], S[b][1]));
            mx1 = fmaxf(mx1, fmaxf(S[b][2], S[b][3]));
        }
        mx0 = fmaxf(mx0, __shfl_xor_sync(0xffffffffu, mx0, 1));
        mx0 = fmaxf(mx0, __shfl_xor_sync(0xffffffffu, mx0, 2));
        mx1 = fmaxf(mx1, __shfl_xor_sync(0xffffffffu, mx1, 1));
        mx1 = fmaxf(mx1, __shfl_xor_sync(0xffffffffu, mx1, 2));

        float mn0 = fmaxf(m0s, mx0);
        float mn1 = fmaxf(m1s, mx1);
        float sc0 = __expf(m0s - mn0);
        float sc1 = __expf(m1s - mn1);

        float rs0 = 0.f, rs1 = 0.f;
#pragma unroll
        for (int b = 0; b < 8; ++b) {
            S[b][0] = __expf(S[b][0] - mn0);
            S[b][1] = __expf(S[b][1] - mn0);
            S[b][2] = __expf(S[b][2] - mn1);
            S[b][3] = __expf(S[b][3] - mn1);
            rs0 += S[b][0] + S[b][1];
            rs1 += S[b][2] + S[b][3];
        }
        rs0 += __shfl_xor_sync(0xffffffffu, rs0, 1);
        rs0 += __shfl_xor_sync(0xffffffffu, rs0, 2);
        rs1 += __shfl_xor_sync(0xffffffffu, rs1, 1);
        rs1 += __shfl_xor_sync(0xffffffffu, rs1, 2);
        l0s = l0s * sc0 + rs0;  m0s = mn0;
        l1s = l1s * sc1 + rs1;  m1s = mn1;

#pragma unroll
        for (int b = 0; b < 16; ++b) {
            O[b][0] *= sc0; O[b][1] *= sc0;
            O[b][2] *= sc1; O[b][3] *= sc1;
        }

#pragma unroll
        for (int kk = 0; kk < 4; ++kk) {
            unsigned pah[4], pal[4];
            split2(S[2 * kk][0],     S[2 * kk][1],     pah[0], pal[0]);
            split2(S[2 * kk][2],     S[2 * kk][3],     pah[1], pal[1]);
            split2(S[2 * kk + 1][0], S[2 * kk + 1][1], pah[2], pal[2]);
            split2(S[2 * kk + 1][2], S[2 * kk + 1][3], pah[3], pal[3]);
#pragma unroll
            for (int bp = 0; bp < 8; ++bp) {
                unsigned vh[4], vl[4];
                ldm4(vh, vsh_a + bp * (16 * VS_STRIDE_B) + kk * 32);
                ldm4(vl, vsl_a + bp * (16 * VS_STRIDE_B) + kk * 32);
                mma16816(O[2 * bp],     pah, vh[0], vh[1]);
                mma16816(O[2 * bp],     pah, vl[0], vl[1]);
                mma16816(O[2 * bp],     pal, vh[0], vh[1]);
                mma16816(O[2 * bp + 1], pah, vh[2], vh[3]);
                mma16816(O[2 * bp + 1], pah, vl[2], vl[3]);
                mma16816(O[2 * bp + 1], pal, vh[2], vh[3]);
            }
        }
    }

    {
        float inv0 = 1.0f / l0s;
        float inv1 = 1.0f / l1s;
        int row0 = s0q + 16 * warp + qr;
        int row1 = row0 + 8;
#pragma unroll
        for (int b = 0; b < 16; ++b) {
            int col = h * DV + 8 * b + qc;
            *(float2*)&out[row0 * DM + col] = make_float2(O[b][0] * inv0, O[b][1] * inv0);
            *(float2*)&out[row1 * DM + col] = make_float2(O[b][2] * inv1, O[b][3] * inv1);
        }
    }
}

// =====================================================================
// launch
// =====================================================================
extern "C" void kernel_launch(void* const* d_in, const int* in_sizes, int n_in,
                              void* d_out, int out_size)
{
    (void)in_sizes; (void)n_in; (void)out_size;
    const float* q   = (const float*)d_in[0];
    const float* k   = (const float*)d_in[1];
    const float* v   = (const float*)d_in[2];
    const float* wq  = (const float*)d_in[3];
    const float* bq  = (const float*)d_in[4];
    const float* wk  = (const float*)d_in[5];
    const float* bk  = (const float*)d_in[6];
    const float* wvr = (const float*)d_in[7];
    const float* bvr = (const float*)d_in[8];
    const float* wvl = (const float*)d_in[9];
    const float* bvl = (const float*)d_in[10];
    float* out = (float*)d_out;

    // 0) convert inputs to bf16 hi/lo
    convert_qkv<<<dim3(SEQ * DM / 1024, 3), 256>>>(q, k, v);
    convert_w  <<<dim3(ZIPD * DM / 1024, 4), 256>>>(wq, wk, wvr, wvl);

    // 1) Q', K', Vr via tensor-core mma (3-term split)
    cudaFuncSetAttribute(proj3_mma, cudaFuncAttributeMaxDynamicSharedMemorySize,
                         PROJ_SMEM_BYTES);
    cudaFuncSetAttribute(projv_mma, cudaFuncAttributeMaxDynamicSharedMemorySize,
                         PROJ_SMEM_BYTES);
    proj3_mma<<<dim3(ZIPD / 64, SEQ / 128, 3), 256, PROJ_SMEM_BYTES>>>(bq, bk, bvr);

    // 2) V^T via tensor-core mma
    projv_mma<<<dim3(SEQ / 64, DM / 128), 256, PROJ_SMEM_BYTES>>>(bvl);

    // 3) tensor-core flash attention
    cudaFuncSetAttribute(flash_kernel, cudaFuncAttributeMaxDynamicSharedMemorySize,
                         FLASH_SMEM_BYTES);
    flash_kernel<<<dim3(SEQ / BQ, HEADS), 128, FLASH_SMEM_BYTES>>>(out);
}